// round 1
// baseline (speedup 1.0000x reference)
#include <cuda_runtime.h>
#include <cstdint>

typedef unsigned long long ull;

static constexpr int BATCH = 16;
static constexpr int NPTS  = 2048;
static constexpr int TOTAL = BATCH * NPTS;   // 32768
static constexpr int KNN   = 6;

// ---------------- scratch (device globals; no cudaMalloc allowed) ----------
__device__ float g_x0[TOTAL * 64];
__device__ float g_x1[TOTAL * 32];
__device__ float g_sq[TOTAL];
__device__ int   g_knn[TOTAL * KNN];

// ---------------- f32x2 helpers --------------------------------------------
__device__ __forceinline__ ull fma2(ull a, ull b, ull c) {
    ull d;
    asm("fma.rn.f32x2 %0, %1, %2, %3;" : "=l"(d) : "l"(a), "l"(b), "l"(c));
    return d;
}
__device__ __forceinline__ ull pack2(float x, float y) {
    ull r;
    asm("mov.b64 %0, {%1, %2};" : "=l"(r) : "f"(x), "f"(y));
    return r;
}
__device__ __forceinline__ void unpack2(ull v, float& x, float& y) {
    asm("mov.b64 {%0, %1}, %2;" : "=f"(x), "=f"(y) : "l"(v));
}

// ---------------- squared norms --------------------------------------------
template <int C>
__global__ void sq_kernel(const float* __restrict__ x, float* __restrict__ sq) {
    int p = blockIdx.x * 256 + threadIdx.x;
    if (p >= TOTAL) return;
    const float4* xp = reinterpret_cast<const float4*>(x + (size_t)p * C);
    float s = 0.f;
#pragma unroll
    for (int i = 0; i < C / 4; i++) {
        float4 v = xp[i];
        s += v.x * v.x + v.y * v.y + v.z * v.z + v.w * v.w;
    }
    sq[p] = s;
}

// ---------------- brute-force kNN (top-6 smallest d2, tie -> lower index) --
// block: 128 threads = 128 queries of one batch; candidates staged in smem in
// feature-paired layout -> 1 LDS.128 per 2 FFMA2.
template <int C>
__global__ void knn_kernel(const float* __restrict__ x,
                           const float* __restrict__ sq,
                           int* __restrict__ knn) {
    constexpr int MT = 16;            // candidates per tile
    constexpr int SP = MT * 2 + 4;    // float stride per feature-pair row (pad, 16B-mult)
    __shared__ __align__(16) float scs[(C / 2) * SP];
    __shared__ float ssq[MT];

    const int b   = blockIdx.y;
    const int tid = threadIdx.x;
    const int q   = blockIdx.x * 128 + tid;          // 0..2047
    const float* xb = x + (size_t)b * NPTS * C;

    // query features into registers (packed pairs)
    ull qf[C / 2];
#pragma unroll
    for (int ip = 0; ip < C / 2; ip++) {
        float2 v = *reinterpret_cast<const float2*>(xb + (size_t)q * C + ip * 2);
        qf[ip] = pack2(v.x, v.y);
    }
    const float qsq = sq[b * NPTS + q];

    const float INF = __int_as_float(0x7f800000);
    float kd[6] = {INF, INF, INF, INF, INF, INF};
    int   ki[6] = {0, 0, 0, 0, 0, 0};

    for (int m0 = 0; m0 < NPTS; m0 += MT) {
        __syncthreads();
        // stage candidate tile, paired layout: scs[(i/2)*SP + mm*2 + (i&1)]
#pragma unroll
        for (int n = 0; n < MT * C / 128; n++) {
            int idx = tid + n * 128;
            int mm  = idx / C;
            int i   = idx % C;
            scs[(i >> 1) * SP + mm * 2 + (i & 1)] = xb[(size_t)(m0 + mm) * C + i];
        }
        if (tid < MT) ssq[tid] = sq[b * NPTS + m0 + tid];
        __syncthreads();

        ull acc[MT];
#pragma unroll
        for (int mm = 0; mm < MT; mm++) acc[mm] = 0ull;

#pragma unroll
        for (int ip = 0; ip < C / 2; ip++) {
            ull qv = qf[ip];
            const ulonglong2* base =
                reinterpret_cast<const ulonglong2*>(scs + ip * SP);
#pragma unroll
            for (int mm2 = 0; mm2 < MT / 2; mm2++) {
                ulonglong2 cc = base[mm2];
                acc[2 * mm2]     = fma2(qv, cc.x, acc[2 * mm2]);
                acc[2 * mm2 + 1] = fma2(qv, cc.y, acc[2 * mm2 + 1]);
            }
        }

#pragma unroll
        for (int mm = 0; mm < MT; mm++) {
            float lo, hi;
            unpack2(acc[mm], lo, hi);
            float d = qsq + ssq[mm] - 2.f * (lo + hi);
            int m = m0 + mm;
            if (m != q && d < kd[5]) {   // strict < keeps lower index on ties
                kd[5] = d; ki[5] = m;
#pragma unroll
                for (int j = 5; j > 0; j--) {
                    if (kd[j] < kd[j - 1]) {   // strict < => stable for equals
                        float td = kd[j]; kd[j] = kd[j - 1]; kd[j - 1] = td;
                        int   ti = ki[j]; ki[j] = ki[j - 1]; ki[j - 1] = ti;
                    }
                }
            }
        }
    }
#pragma unroll
    for (int k = 0; k < KNN; k++)
        knn[(size_t)(b * NPTS + q) * KNN + k] = b * NPTS + ki[k];
}

// ---------------- edge MLP + max over K + (residual) + relu ----------------
// warp per point; weights pre-packed (feature pairs) in smem for f32x2.
template <int CIN, int H, int COUT, bool RES>
__global__ void edge_kernel(const float* __restrict__ x,
                            const int* __restrict__ knn,
                            const float* __restrict__ W1,
                            const float* __restrict__ b1,
                            const float* __restrict__ W2,
                            const float* __restrict__ b2,
                            const float* __restrict__ res,
                            float* __restrict__ out) {
    constexpr int WPB = 8;            // warps (points) per block
    constexpr int P1  = CIN;          // (2*CIN)/2 feature pairs for W1
    constexpr int P2  = H / 2;        // pairs for W2
    constexpr int CH  = H / 32;       // h1 channels per lane
    constexpr int CO  = COUT / 32;    // out channels per lane

    __shared__ ull W1p[P1 * H];       // (pair ip, chan c): {W1[2ip][c], W1[2ip+1][c]}
    __shared__ ull W2p[P2 * COUT];
    __shared__ __align__(16) ull mgu[WPB][CIN];      // msg (2*CIN floats) per warp
    __shared__ __align__(16) ull hbu[WPB][H / 2];    // h1   (H floats)    per warp

    const int tid  = threadIdx.x;
    const int w    = tid >> 5;
    const int lane = tid & 31;

    for (int idx = tid; idx < P1 * H; idx += 256) {
        int ip = idx / H, c = idx % H;
        W1p[idx] = pack2(W1[(2 * ip) * H + c], W1[(2 * ip + 1) * H + c]);
    }
    for (int idx = tid; idx < P2 * COUT; idx += 256) {
        int hp = idx / COUT, c = idx % COUT;
        W2p[idx] = pack2(W2[(2 * hp) * COUT + c], W2[(2 * hp + 1) * COUT + c]);
    }
    __syncthreads();

    const int P = blockIdx.x * WPB + w;
    float* mg = reinterpret_cast<float*>(mgu[w]);
    float* hb = reinterpret_cast<float*>(hbu[w]);

    float b1v[CH], b2v[CO];
#pragma unroll
    for (int cc = 0; cc < CH; cc++) b1v[cc] = b1[lane + 32 * cc];
#pragma unroll
    for (int cc = 0; cc < CO; cc++) b2v[cc] = b2[lane + 32 * cc];

    // msg first half: xi (constant over edges)
#pragma unroll
    for (int i = lane; i < CIN; i += 32) mg[i] = x[(size_t)P * CIN + i];

    const float NINF = __int_as_float(0xff800000);
    float best[CO];
#pragma unroll
    for (int cc = 0; cc < CO; cc++) best[cc] = NINF;

    for (int k = 0; k < KNN; k++) {
        int j = knn[(size_t)P * KNN + k];
        __syncwarp();
#pragma unroll
        for (int i = lane; i < CIN; i += 32)
            mg[CIN + i] = x[(size_t)j * CIN + i] - mg[i];
        __syncwarp();

        // stage 1: h1 = relu(msg @ W1 + b1)
        ull a2[CH];
#pragma unroll
        for (int cc = 0; cc < CH; cc++) a2[cc] = 0ull;
#pragma unroll
        for (int ip = 0; ip < P1; ip++) {
            ull mv = mgu[w][ip];
#pragma unroll
            for (int cc = 0; cc < CH; cc++)
                a2[cc] = fma2(mv, W1p[ip * H + lane + 32 * cc], a2[cc]);
        }
        __syncwarp();
#pragma unroll
        for (int cc = 0; cc < CH; cc++) {
            float lo, hi;
            unpack2(a2[cc], lo, hi);
            hb[lane + 32 * cc] = fmaxf(b1v[cc] + lo + hi, 0.f);
        }
        __syncwarp();

        // stage 2: o = h1 @ W2 + b2 ; best = max(best, o)
        ull o2[CO];
#pragma unroll
        for (int cc = 0; cc < CO; cc++) o2[cc] = 0ull;
#pragma unroll
        for (int hp = 0; hp < P2; hp++) {
            ull hv = hbu[w][hp];
#pragma unroll
            for (int cc = 0; cc < CO; cc++)
                o2[cc] = fma2(hv, W2p[hp * COUT + lane + 32 * cc], o2[cc]);
        }
#pragma unroll
        for (int cc = 0; cc < CO; cc++) {
            float lo, hi;
            unpack2(o2[cc], lo, hi);
            best[cc] = fmaxf(best[cc], b2v[cc] + lo + hi);
        }
    }

#pragma unroll
    for (int cc = 0; cc < CO; cc++) {
        int c = lane + 32 * cc;
        float v = best[cc];
        if (RES) v += res[(size_t)P * COUT + c];
        out[(size_t)P * COUT + c] = fmaxf(v, 0.f);
    }
}

// ---------------- launch ----------------------------------------------------
extern "C" void kernel_launch(void* const* d_in, const int* in_sizes, int n_in,
                              void* d_out, int out_size) {
    const float* x    = (const float*)d_in[0];
    // d_in[1] = batch (unused; fixed layout)
    const float* W1_0 = (const float*)d_in[2];
    const float* b1_0 = (const float*)d_in[3];
    const float* W2_0 = (const float*)d_in[4];
    const float* b2_0 = (const float*)d_in[5];
    const float* W1_1 = (const float*)d_in[6];
    const float* b1_1 = (const float*)d_in[7];
    const float* W2_1 = (const float*)d_in[8];
    const float* b2_1 = (const float*)d_in[9];
    const float* W1_2 = (const float*)d_in[10];
    const float* b1_2 = (const float*)d_in[11];
    const float* W2_2 = (const float*)d_in[12];
    const float* b2_2 = (const float*)d_in[13];
    float* out = (float*)d_out;

    float *px0, *px1, *psq;
    int* pknn;
    cudaGetSymbolAddress((void**)&px0, g_x0);
    cudaGetSymbolAddress((void**)&px1, g_x1);
    cudaGetSymbolAddress((void**)&psq, g_sq);
    cudaGetSymbolAddress((void**)&pknn, g_knn);

    dim3 knn_grid(NPTS / 128, BATCH);

    // ---- layer 0: x(32) -> x0(64), relu
    sq_kernel<32><<<TOTAL / 256, 256>>>(x, psq);
    knn_kernel<32><<<knn_grid, 128>>>(x, psq, pknn);
    edge_kernel<32, 64, 64, false><<<TOTAL / 8, 256>>>(
        x, pknn, W1_0, b1_0, W2_0, b2_0, nullptr, px0);

    // ---- layer 1: x0(64) -> x1(32), relu
    sq_kernel<64><<<TOTAL / 256, 256>>>(px0, psq);
    knn_kernel<64><<<knn_grid, 128>>>(px0, psq, pknn);
    edge_kernel<64, 32, 32, false><<<TOTAL / 8, 256>>>(
        px0, pknn, W1_1, b1_1, W2_1, b2_1, nullptr, px1);

    // ---- layer 2: x1(32) -> out(64) = relu(conv + x0)
    sq_kernel<32><<<TOTAL / 256, 256>>>(px1, psq);
    knn_kernel<32><<<knn_grid, 128>>>(px1, psq, pknn);
    edge_kernel<32, 64, 64, true><<<TOTAL / 8, 256>>>(
        px1, pknn, W1_2, b1_2, W2_2, b2_2, px0, out);
}

// round 2
// speedup vs baseline: 1.6062x; 1.6062x over previous
#include <cuda_runtime.h>
#include <cstdint>

typedef unsigned long long ull;

static constexpr int BATCH  = 16;
static constexpr int NPTS   = 2048;
static constexpr int TOTAL  = BATCH * NPTS;    // 32768
static constexpr int KNN    = 6;
static constexpr int NSPLIT = 4;
static constexpr int CHUNK  = NPTS / NSPLIT;   // 512

// ---------------- scratch (device globals; no cudaMalloc allowed) ----------
__device__ float g_x0[TOTAL * 64];
__device__ float g_x1[TOTAL * 32];
__device__ float g_sq[TOTAL];
__device__ int   g_knn[TOTAL * KNN];
__device__ float g_pd[TOTAL * NSPLIT * KNN];
__device__ int   g_pi[TOTAL * NSPLIT * KNN];

// ---------------- f32x2 helpers --------------------------------------------
__device__ __forceinline__ ull fma2(ull a, ull b, ull c) {
    ull d;
    asm("fma.rn.f32x2 %0, %1, %2, %3;" : "=l"(d) : "l"(a), "l"(b), "l"(c));
    return d;
}
__device__ __forceinline__ ull pack2(float x, float y) {
    ull r;
    asm("mov.b64 %0, {%1, %2};" : "=l"(r) : "f"(x), "f"(y));
    return r;
}
__device__ __forceinline__ void unpack2(ull v, float& x, float& y) {
    asm("mov.b64 {%0, %1}, %2;" : "=f"(x), "=f"(y) : "l"(v));
}

// ---------------- squared norms --------------------------------------------
template <int C>
__global__ void sq_kernel(const float* __restrict__ x, float* __restrict__ sq) {
    int p = blockIdx.x * 256 + threadIdx.x;
    if (p >= TOTAL) return;
    const float4* xp = reinterpret_cast<const float4*>(x + (size_t)p * C);
    float s = 0.f;
#pragma unroll
    for (int i = 0; i < C / 4; i++) {
        float4 v = xp[i];
        s += v.x * v.x + v.y * v.y + v.z * v.z + v.w * v.w;
    }
    sq[p] = s;
}

// ---------------- partial kNN over one candidate chunk ---------------------
// block: 128 queries of one batch; chunk of 512 candidates staged in smem in
// feature-paired layout -> LDS.128 broadcast feeding 2 FFMA2 each.
template <int C>
__global__ void __launch_bounds__(128)
knn_part_kernel(const float* __restrict__ x,
                const float* __restrict__ sq,
                float* __restrict__ pd, int* __restrict__ pi) {
    constexpr int MT = 16;            // candidates per tile
    constexpr int SP = MT * 2 + 4;    // float stride per feature-pair row
    __shared__ __align__(16) float scs[(C / 2) * SP];
    __shared__ float ssq[MT];

    const int b     = blockIdx.y;
    const int chunk = blockIdx.z;
    const int tid   = threadIdx.x;
    const int q     = blockIdx.x * 128 + tid;
    const float* xb = x + (size_t)b * NPTS * C;

    ull qf[C / 2];
#pragma unroll
    for (int ip = 0; ip < C / 2; ip++) {
        float2 v = *reinterpret_cast<const float2*>(xb + (size_t)q * C + ip * 2);
        qf[ip] = pack2(v.x, v.y);
    }
    const float qsq = sq[b * NPTS + q];

    const float INF = __int_as_float(0x7f800000);
    float kd[6] = {INF, INF, INF, INF, INF, INF};
    int   ki[6] = {0, 0, 0, 0, 0, 0};

    const int m_beg = chunk * CHUNK;
    for (int m0 = m_beg; m0 < m_beg + CHUNK; m0 += MT) {
        __syncthreads();
#pragma unroll
        for (int n = 0; n < MT * C / 128; n++) {
            int idx = tid + n * 128;
            int mm  = idx / C;
            int i   = idx % C;
            scs[(i >> 1) * SP + mm * 2 + (i & 1)] = xb[(size_t)(m0 + mm) * C + i];
        }
        if (tid < MT) ssq[tid] = sq[b * NPTS + m0 + tid];
        __syncthreads();

        ull acc[MT];
#pragma unroll
        for (int mm = 0; mm < MT; mm++) acc[mm] = 0ull;

#pragma unroll
        for (int ip = 0; ip < C / 2; ip++) {
            ull qv = qf[ip];
            const ulonglong2* base =
                reinterpret_cast<const ulonglong2*>(scs + ip * SP);
#pragma unroll
            for (int mm2 = 0; mm2 < MT / 2; mm2++) {
                ulonglong2 cc = base[mm2];
                acc[2 * mm2]     = fma2(qv, cc.x, acc[2 * mm2]);
                acc[2 * mm2 + 1] = fma2(qv, cc.y, acc[2 * mm2 + 1]);
            }
        }

#pragma unroll
        for (int mm = 0; mm < MT; mm++) {
            float lo, hi;
            unpack2(acc[mm], lo, hi);
            float d = qsq + ssq[mm] - 2.f * (lo + hi);
            int m = m0 + mm;
            if (m != q && d < kd[5]) {   // strict < keeps lower index on ties
                kd[5] = d; ki[5] = m;
#pragma unroll
                for (int j = 5; j > 0; j--) {
                    if (kd[j] < kd[j - 1]) {
                        float td = kd[j]; kd[j] = kd[j - 1]; kd[j - 1] = td;
                        int   ti = ki[j]; ki[j] = ki[j - 1]; ki[j - 1] = ti;
                    }
                }
            }
        }
    }
    const int base = ((b * NPTS + q) * NSPLIT + chunk) * KNN;
#pragma unroll
    for (int k = 0; k < KNN; k++) {
        pd[base + k] = kd[k];
        pi[base + k] = b * NPTS + ki[k];
    }
}

// ---------------- merge NSPLIT partial top-6 lists --------------------------
// Entries arrive in chunk order (ascending candidate index ranges), each list
// ascending distance with ties already lower-index-first; strict-< insertion
// therefore reproduces global top_k tie-breaking for set membership.
__global__ void knn_merge_kernel(const float* __restrict__ pd,
                                 const int* __restrict__ pi,
                                 int* __restrict__ knn) {
    int p = blockIdx.x * 256 + threadIdx.x;
    if (p >= TOTAL) return;
    const float INF = __int_as_float(0x7f800000);
    float kd[6] = {INF, INF, INF, INF, INF, INF};
    int   ki[6] = {0, 0, 0, 0, 0, 0};
    const int base = p * NSPLIT * KNN;
#pragma unroll
    for (int e = 0; e < NSPLIT * KNN; e++) {
        float d = pd[base + e];
        int   i = pi[base + e];
        if (d < kd[5]) {
            kd[5] = d; ki[5] = i;
#pragma unroll
            for (int j = 5; j > 0; j--) {
                if (kd[j] < kd[j - 1]) {
                    float td = kd[j]; kd[j] = kd[j - 1]; kd[j - 1] = td;
                    int   ti = ki[j]; ki[j] = ki[j - 1]; ki[j - 1] = ti;
                }
            }
        }
    }
#pragma unroll
    for (int k = 0; k < KNN; k++) knn[p * KNN + k] = ki[k];
}

// ---------------- edge MLP + max over K + (residual) + relu ----------------
// warp per point (8 points/warp); loops are feature-outer / edge-inner so each
// weight LDS feeds 6 fma2; the xi half of stage-1 is computed once per point.
template <int CIN, int H, int COUT, bool RES>
__global__ void __launch_bounds__(128)
edge_kernel(const float* __restrict__ x,
            const int* __restrict__ knn,
            const float* __restrict__ W1, const float* __restrict__ b1,
            const float* __restrict__ W2, const float* __restrict__ b2,
            const float* __restrict__ res, float* __restrict__ out) {
    constexpr int WPB = 4;            // warps per block
    constexpr int PPW = 8;            // points per warp
    constexpr int CH  = H / 32;       // h1 channels per lane
    constexpr int CO  = COUT / 32;    // out channels per lane
    constexpr int RIN = CIN / 32;     // input features per lane

    __shared__ ull W1p[CIN * H];              // pair-row q -> rows (2q,2q+1)
    __shared__ ull W2p[(H / 2) * COUT];
    __shared__ __align__(16) ull xiu[WPB][CIN / 2];
    __shared__ __align__(16) ull dgu[WPB][KNN][CIN / 2];
    __shared__ __align__(16) ull hbu[WPB][KNN][H / 2];

    const int tid  = threadIdx.x;
    const int w    = tid >> 5;
    const int lane = tid & 31;

    for (int idx = tid; idx < CIN * H; idx += 128) {
        int q = idx / H, c = idx % H;
        W1p[idx] = pack2(W1[(2 * q) * H + c], W1[(2 * q + 1) * H + c]);
    }
    for (int idx = tid; idx < (H / 2) * COUT; idx += 128) {
        int q = idx / COUT, c = idx % COUT;
        W2p[idx] = pack2(W2[(2 * q) * COUT + c], W2[(2 * q + 1) * COUT + c]);
    }
    __syncthreads();

    float b1v[CH], b2v[CO];
#pragma unroll
    for (int cc = 0; cc < CH; cc++) b1v[cc] = b1[lane + 32 * cc];
#pragma unroll
    for (int cc = 0; cc < CO; cc++) b2v[cc] = b2[lane + 32 * cc];

    float* xif = reinterpret_cast<float*>(xiu[w]);
    const float NINF = __int_as_float(0xff800000);
    const int p0 = (blockIdx.x * WPB + w) * PPW;

    for (int pt = 0; pt < PPW; pt++) {
        const int P = p0 + pt;

        // xi + neighbor diffs into per-warp smem
        float xr[RIN];
#pragma unroll
        for (int r = 0; r < RIN; r++) {
            xr[r] = x[(size_t)P * CIN + lane + 32 * r];
            xif[lane + 32 * r] = xr[r];
        }
#pragma unroll
        for (int k = 0; k < KNN; k++) {
            int j = knn[P * KNN + k];
            float* dgf = reinterpret_cast<float*>(dgu[w][k]);
#pragma unroll
            for (int r = 0; r < RIN; r++)
                dgf[lane + 32 * r] = x[(size_t)j * CIN + lane + 32 * r] - xr[r];
        }
        __syncwarp();

        // stage 1 base: xi @ W1[:CIN] (edge-invariant)
        ull ab[CH];
#pragma unroll
        for (int cc = 0; cc < CH; cc++) ab[cc] = 0ull;
#pragma unroll
        for (int ip = 0; ip < CIN / 2; ip++) {
            ull xv = xiu[w][ip];
#pragma unroll
            for (int cc = 0; cc < CH; cc++)
                ab[cc] = fma2(xv, W1p[ip * H + lane + 32 * cc], ab[cc]);
        }

        // stage 1 per edge: + (xj-xi) @ W1[CIN:]
        ull a2[KNN][CH];
#pragma unroll
        for (int k = 0; k < KNN; k++)
#pragma unroll
            for (int cc = 0; cc < CH; cc++) a2[k][cc] = ab[cc];
#pragma unroll
        for (int ip = 0; ip < CIN / 2; ip++) {
            ull wv[CH];
#pragma unroll
            for (int cc = 0; cc < CH; cc++)
                wv[cc] = W1p[(CIN / 2 + ip) * H + lane + 32 * cc];
#pragma unroll
            for (int k = 0; k < KNN; k++) {
                ull dv = dgu[w][k][ip];
#pragma unroll
                for (int cc = 0; cc < CH; cc++)
                    a2[k][cc] = fma2(dv, wv[cc], a2[k][cc]);
            }
        }
#pragma unroll
        for (int k = 0; k < KNN; k++) {
            float* hbf = reinterpret_cast<float*>(hbu[w][k]);
#pragma unroll
            for (int cc = 0; cc < CH; cc++) {
                float lo, hi;
                unpack2(a2[k][cc], lo, hi);
                hbf[lane + 32 * cc] = fmaxf(b1v[cc] + lo + hi, 0.f);
            }
        }
        __syncwarp();

        // stage 2: o = h1 @ W2 + b2, max over edges
        ull o2[KNN][CO];
#pragma unroll
        for (int k = 0; k < KNN; k++)
#pragma unroll
            for (int cc = 0; cc < CO; cc++) o2[k][cc] = 0ull;
#pragma unroll
        for (int hp = 0; hp < H / 2; hp++) {
            ull wv[CO];
#pragma unroll
            for (int cc = 0; cc < CO; cc++)
                wv[cc] = W2p[hp * COUT + lane + 32 * cc];
#pragma unroll
            for (int k = 0; k < KNN; k++) {
                ull hv = hbu[w][k][hp];
#pragma unroll
                for (int cc = 0; cc < CO; cc++)
                    o2[k][cc] = fma2(hv, wv[cc], o2[k][cc]);
            }
        }
        float best[CO];
#pragma unroll
        for (int cc = 0; cc < CO; cc++) best[cc] = NINF;
#pragma unroll
        for (int k = 0; k < KNN; k++)
#pragma unroll
            for (int cc = 0; cc < CO; cc++) {
                float lo, hi;
                unpack2(o2[k][cc], lo, hi);
                best[cc] = fmaxf(best[cc], b2v[cc] + lo + hi);
            }

#pragma unroll
        for (int cc = 0; cc < CO; cc++) {
            int c = lane + 32 * cc;
            float v = best[cc];
            if (RES) v += res[(size_t)P * COUT + c];
            out[(size_t)P * COUT + c] = fmaxf(v, 0.f);
        }
        __syncwarp();
    }
}

// ---------------- launch ----------------------------------------------------
extern "C" void kernel_launch(void* const* d_in, const int* in_sizes, int n_in,
                              void* d_out, int out_size) {
    const float* x    = (const float*)d_in[0];
    const float* W1_0 = (const float*)d_in[2];
    const float* b1_0 = (const float*)d_in[3];
    const float* W2_0 = (const float*)d_in[4];
    const float* b2_0 = (const float*)d_in[5];
    const float* W1_1 = (const float*)d_in[6];
    const float* b1_1 = (const float*)d_in[7];
    const float* W2_1 = (const float*)d_in[8];
    const float* b2_1 = (const float*)d_in[9];
    const float* W1_2 = (const float*)d_in[10];
    const float* b1_2 = (const float*)d_in[11];
    const float* W2_2 = (const float*)d_in[12];
    const float* b2_2 = (const float*)d_in[13];
    float* out = (float*)d_out;

    float *px0, *px1, *psq, *ppd;
    int *pknn, *ppi;
    cudaGetSymbolAddress((void**)&px0, g_x0);
    cudaGetSymbolAddress((void**)&px1, g_x1);
    cudaGetSymbolAddress((void**)&psq, g_sq);
    cudaGetSymbolAddress((void**)&pknn, g_knn);
    cudaGetSymbolAddress((void**)&ppd, g_pd);
    cudaGetSymbolAddress((void**)&ppi, g_pi);

    dim3 knn_grid(NPTS / 128, BATCH, NSPLIT);
    const int edge_grid = TOTAL / (4 * 8);   // WPB*PPW points per block

    // ---- layer 0: x(32) -> x0(64), relu
    sq_kernel<32><<<TOTAL / 256, 256>>>(x, psq);
    knn_part_kernel<32><<<knn_grid, 128>>>(x, psq, ppd, ppi);
    knn_merge_kernel<<<TOTAL / 256, 256>>>(ppd, ppi, pknn);
    edge_kernel<32, 64, 64, false><<<edge_grid, 128>>>(
        x, pknn, W1_0, b1_0, W2_0, b2_0, nullptr, px0);

    // ---- layer 1: x0(64) -> x1(32), relu
    sq_kernel<64><<<TOTAL / 256, 256>>>(px0, psq);
    knn_part_kernel<64><<<knn_grid, 128>>>(px0, psq, ppd, ppi);
    knn_merge_kernel<<<TOTAL / 256, 256>>>(ppd, ppi, pknn);
    edge_kernel<64, 32, 32, false><<<edge_grid, 128>>>(
        px0, pknn, W1_1, b1_1, W2_1, b2_1, nullptr, px1);

    // ---- layer 2: x1(32) -> out(64) = relu(conv + x0)
    sq_kernel<32><<<TOTAL / 256, 256>>>(px1, psq);
    knn_part_kernel<32><<<knn_grid, 128>>>(px1, psq, ppd, ppi);
    knn_merge_kernel<<<TOTAL / 256, 256>>>(ppd, ppi, pknn);
    edge_kernel<32, 64, 64, true><<<edge_grid, 128>>>(
        px1, pknn, W1_2, b1_2, W2_2, b2_2, px0, out);
}